// round 15
// baseline (speedup 1.0000x reference)
#include <cuda_runtime.h>
#include <cuda_bf16.h>
#include <cstdint>
#include <cstddef>

// Problem constants
// x: [B=4, C=256, H=256, W=256], tokens M = B*H*W = 262144
#define M_TOK 262144
#define CDIM 256
#define HEADS 8
#define HD 32
#define WIN 8
#define TWIN 64
#define NWIN 4096

// ---------------------------------------------------------------------------
// Scratch (static __device__ arrays — allocation-free per harness rules)
// ---------------------------------------------------------------------------
__device__ float g_qkv[(size_t)M_TOK * 768];          // 805 MB
__device__ float g_proj[(size_t)M_TOK * CDIM];        // 268 MB
__device__ __nv_bfloat16 g_xh[(size_t)M_TOK * CDIM];  // x transposed, hi
__device__ __nv_bfloat16 g_xl[(size_t)M_TOK * CDIM];  // x transposed, lo
__device__ __nv_bfloat16 g_oh[(size_t)M_TOK * CDIM];  // attn out, hi
__device__ __nv_bfloat16 g_ol[(size_t)M_TOK * CDIM];  // attn out, lo
__device__ __nv_bfloat16 g_wih[768 * 256], g_wil[768 * 256];
__device__ __nv_bfloat16 g_woh[256 * 256], g_wol[256 * 256];

// ---------------------------------------------------------------------------
// PTX helpers (compute_103-safe: cp.async + ldmatrix + mma.sync only)
// ---------------------------------------------------------------------------
__device__ __forceinline__ uint32_t smem_u32(const void* p) {
    uint32_t a;
    asm("{ .reg .u64 t; cvta.to.shared.u64 t, %1; cvt.u32.u64 %0, t; }"
        : "=r"(a) : "l"(p));
    return a;
}

__device__ __forceinline__ void cp16(uint32_t dst, const void* src) {
    asm volatile("cp.async.cg.shared.global [%0], [%1], 16;"
                 :: "r"(dst), "l"(src));
}

#define LDSM4(r, a) \
    asm volatile("ldmatrix.sync.aligned.m8n8.x4.shared.b16 {%0,%1,%2,%3}, [%4];" \
        : "=r"((r)[0]), "=r"((r)[1]), "=r"((r)[2]), "=r"((r)[3]) : "r"(a))

#define MMA16816(c, a, b0, b1) \
    asm volatile("mma.sync.aligned.m16n8k16.row.col.f32.bf16.bf16.f32 " \
        "{%0,%1,%2,%3}, {%4,%5,%6,%7}, {%8,%9}, {%0,%1,%2,%3};" \
        : "+f"((c)[0]), "+f"((c)[1]), "+f"((c)[2]), "+f"((c)[3]) \
        : "r"((a)[0]), "r"((a)[1]), "r"((a)[2]), "r"((a)[3]), "r"(b0), "r"(b1))

// ---------------------------------------------------------------------------
// Split kernels: fp32 -> (bf16 hi, bf16 lo)
// ---------------------------------------------------------------------------
__global__ __launch_bounds__(256) void split_small_kernel(
    const float* __restrict__ in, __nv_bfloat16* __restrict__ hi,
    __nv_bfloat16* __restrict__ lo, int n)
{
    int i = blockIdx.x * 256 + threadIdx.x;
    if (i < n) {
        float v = in[i];
        __nv_bfloat16 h = __float2bfloat16(v);
        hi[i] = h;
        lo[i] = __float2bfloat16(v - __bfloat162float(h));
    }
}

// x [4][256][65536] NCHW -> xT [m][256] bf16 hi/lo (transpose + split)
__global__ __launch_bounds__(256) void split_x_kernel(
    const float* __restrict__ x, __nv_bfloat16* __restrict__ hi,
    __nv_bfloat16* __restrict__ lo)
{
    __shared__ float s[32][132];
    const int tid = threadIdx.x;
    const int m0 = blockIdx.x * 128;
    const int c0 = blockIdx.y * 32;
    const int b = m0 >> 16;
    const int hw0 = m0 & 65535;
    const float* xb = x + ((size_t)b * 256 + c0) * 65536 + hw0;

    #pragma unroll
    for (int i = 0; i < 4; i++) {
        int idx = tid + 256 * i;       // 1024 float4 slots = 32c x 32(m4)
        int c = idx >> 5, m4 = idx & 31;
        float4 v = *(const float4*)(xb + (size_t)c * 65536 + m4 * 4);
        *(float4*)&s[c][m4 * 4] = v;
    }
    __syncthreads();

    const int m = tid >> 1;
    const int half = tid & 1;
    uint32_t hp[8], lp[8];
    #pragma unroll
    for (int p = 0; p < 8; p++) {
        float a = s[half * 16 + 2 * p][m];
        float bb = s[half * 16 + 2 * p + 1][m];
        __nv_bfloat162 hh = __floats2bfloat162_rn(a, bb);
        float ra = a - __bfloat162float(hh.x);
        float rb = bb - __bfloat162float(hh.y);
        __nv_bfloat162 ll = __floats2bfloat162_rn(ra, rb);
        hp[p] = *reinterpret_cast<uint32_t*>(&hh);
        lp[p] = *reinterpret_cast<uint32_t*>(&ll);
    }
    size_t o = (size_t)(m0 + m) * 256 + c0 + half * 16;
    ((uint4*)(hi + o))[0] = make_uint4(hp[0], hp[1], hp[2], hp[3]);
    ((uint4*)(hi + o))[1] = make_uint4(hp[4], hp[5], hp[6], hp[7]);
    ((uint4*)(lo + o))[0] = make_uint4(lp[0], lp[1], lp[2], lp[3]);
    ((uint4*)(lo + o))[1] = make_uint4(lp[4], lp[5], lp[6], lp[7]);
}

// ---------------------------------------------------------------------------
// bf16 mma.sync GEMM: out[m, n] = sum_k A[m,k]*B[n,k] + bias[n]
//  A,B as bf16 hi/lo pairs, K = 256. CTA tile 128x128, BK=32, 2-stage cp.async.
//  3-term compensated product: Ah*Bh + Ah*Bl + Al*Bh (fp32 accum).
//  8 warps (4m x 2n), each 32x64 via m16n8k16.
//  SMEM tiles: 128 rows x 40 bf16 (stride 80B -> conflict-free ldmatrix).
// ---------------------------------------------------------------------------
#define TILE_B 10240           // 128 * 80 bytes
#define STAGE_B (4 * TILE_B)   // Ah, Al, Bh, Bl
#define GEMM_SMEM (2 * STAGE_B)

__device__ __forceinline__ void load_tile32(uint32_t dst, const __nv_bfloat16* src,
                                            int r0, int k0, int tid) {
    #pragma unroll
    for (int i = 0; i < 2; i++) {
        int idx = tid + 256 * i;          // 512 x 16B chunks
        int row = idx >> 2, cc = idx & 3;
        cp16(dst + row * 80 + cc * 16,
             src + (size_t)(r0 + row) * 256 + k0 + cc * 8);
    }
}

__global__ __launch_bounds__(256) void mma_gemm_kernel(
    const __nv_bfloat16* __restrict__ Ah, const __nv_bfloat16* __restrict__ Al,
    const __nv_bfloat16* __restrict__ Bh, const __nv_bfloat16* __restrict__ Bl,
    const float* __restrict__ bias, float* __restrict__ out, int ldout)
{
    extern __shared__ char smem[];
    const int tid = threadIdx.x;
    const int wid = tid >> 5, lane = tid & 31;
    const int wm = wid & 3, wn = wid >> 2;       // 4 x 2 warp grid
    const int n0 = blockIdx.x * 128, m0 = blockIdx.y * 128;
    const uint32_t sb = smem_u32(smem);

    // ldmatrix address components (bytes)
    const uint32_t aRowB = (uint32_t)(wm * 32 + (lane & 15)) * 80 + (lane >> 4) * 16;
    const uint32_t bRowB = (uint32_t)(wn * 64 + (lane >> 4) * 8 + (lane & 7)) * 80
                         + ((lane >> 3) & 1) * 16;

    #define LOAD_STAGE(s) do {                                   \
        int _k = (s) * 32;                                       \
        uint32_t _b = sb + ((s) & 1) * STAGE_B;                  \
        load_tile32(_b,              Ah, m0, _k, tid);           \
        load_tile32(_b + TILE_B,     Al, m0, _k, tid);           \
        load_tile32(_b + 2 * TILE_B, Bh, n0, _k, tid);           \
        load_tile32(_b + 3 * TILE_B, Bl, n0, _k, tid);           \
        asm volatile("cp.async.commit_group;" ::: "memory");     \
    } while (0)

    LOAD_STAGE(0);
    LOAD_STAGE(1);

    float c[2][8][4];
    #pragma unroll
    for (int mi = 0; mi < 2; mi++)
        #pragma unroll
        for (int nj = 0; nj < 8; nj++)
            #pragma unroll
            for (int q = 0; q < 4; q++) c[mi][nj][q] = 0.f;

    #pragma unroll 1
    for (int s = 0; s < 8; s++) {
        if (s < 7) asm volatile("cp.async.wait_group 1;" ::: "memory");
        else       asm volatile("cp.async.wait_group 0;" ::: "memory");
        __syncthreads();

        const uint32_t base = sb + (s & 1) * STAGE_B;
        #pragma unroll
        for (int kk = 0; kk < 2; kk++) {
            const uint32_t ko = kk * 32;   // 16 bf16 = 32 bytes
            uint32_t ah[2][4], al[2][4], bh[4][4], bl[4][4];
            #pragma unroll
            for (int mi = 0; mi < 2; mi++) {
                uint32_t ra = base + aRowB + mi * 16 * 80 + ko;
                LDSM4(ah[mi], ra);
                LDSM4(al[mi], ra + TILE_B);
            }
            #pragma unroll
            for (int g = 0; g < 4; g++) {
                uint32_t rb = base + 2 * TILE_B + bRowB + g * 16 * 80 + ko;
                LDSM4(bh[g], rb);
                LDSM4(bl[g], rb + TILE_B);
            }
            #pragma unroll
            for (int mi = 0; mi < 2; mi++)
                #pragma unroll
                for (int g = 0; g < 4; g++)
                    #pragma unroll
                    for (int h = 0; h < 2; h++) {
                        float* cc = c[mi][2 * g + h];
                        MMA16816(cc, ah[mi], bh[g][2 * h], bh[g][2 * h + 1]);
                        MMA16816(cc, ah[mi], bl[g][2 * h], bl[g][2 * h + 1]);
                        MMA16816(cc, al[mi], bh[g][2 * h], bh[g][2 * h + 1]);
                    }
        }
        __syncthreads();
        if (s + 2 < 8) LOAD_STAGE(s + 2);
    }
    #undef LOAD_STAGE

    // Epilogue: bias + float2 fragment stores
    #pragma unroll
    for (int mi = 0; mi < 2; mi++) {
        const int row = m0 + wm * 32 + mi * 16 + (lane >> 2);
        #pragma unroll
        for (int nj = 0; nj < 8; nj++) {
            const int col = n0 + wn * 64 + nj * 8 + (lane & 3) * 2;
            const float2 bv = *(const float2*)(bias + col);
            float2 v0 = make_float2(c[mi][nj][0] + bv.x, c[mi][nj][1] + bv.y);
            float2 v1 = make_float2(c[mi][nj][2] + bv.x, c[mi][nj][3] + bv.y);
            *(float2*)(out + (size_t)row * ldout + col) = v0;
            *(float2*)(out + (size_t)(row + 8) * ldout + col) = v1;
        }
    }
}

// ---------------------------------------------------------------------------
// Windowed attention (fp32). One 64-thread block per (window, head).
// Outputs bf16 hi/lo directly for the out-proj GEMM.
// ---------------------------------------------------------------------------
__global__ __launch_bounds__(64) void attn_kernel(
    const float* __restrict__ qkv,
    __nv_bfloat16* __restrict__ o_hi, __nv_bfloat16* __restrict__ o_lo)
{
    const int bid = blockIdx.x;
    const int head = bid & 7;
    const int win = bid >> 3;
    const int b = win >> 10;
    const int rem = win & 1023;
    const int hn = rem >> 5, wn = rem & 31;

    const int t = threadIdx.x;
    const int s1 = t >> 3, s2 = t & 7;
    const int m = (b << 16) + ((hn * 8 + s1) << 8) + (wn * 8 + s2);

    __shared__ float4 ks[TWIN][8];
    __shared__ float4 vs[TWIN][8];

    const float* qp = qkv + (size_t)m * 768 + head * 32;
    float4 q[8];
    #pragma unroll
    for (int d = 0; d < 8; d++) {
        q[d]     = ((const float4*)(qp))[d];
        ks[t][d] = ((const float4*)(qp + 256))[d];
        vs[t][d] = ((const float4*)(qp + 512))[d];
    }
    __syncthreads();

    float s[TWIN];
    #pragma unroll
    for (int j = 0; j < TWIN; j++) {
        float acc = 0.f;
        #pragma unroll
        for (int d = 0; d < 8; d++) {
            float4 kv = ks[j][d];
            acc = fmaf(q[d].x, kv.x, acc);
            acc = fmaf(q[d].y, kv.y, acc);
            acc = fmaf(q[d].z, kv.z, acc);
            acc = fmaf(q[d].w, kv.w, acc);
        }
        s[j] = acc * 0.17677669529663687f;
    }

    float mx = s[0];
    #pragma unroll
    for (int j = 1; j < TWIN; j++) mx = fmaxf(mx, s[j]);
    float sum = 0.f;
    #pragma unroll
    for (int j = 0; j < TWIN; j++) { s[j] = __expf(s[j] - mx); sum += s[j]; }
    const float inv = 1.f / sum;

    float4 acc4[8];
    #pragma unroll
    for (int d = 0; d < 8; d++) acc4[d] = make_float4(0.f, 0.f, 0.f, 0.f);
    #pragma unroll
    for (int j = 0; j < TWIN; j++) {
        const float p = s[j] * inv;
        #pragma unroll
        for (int d = 0; d < 8; d++) {
            float4 vv = vs[j][d];
            acc4[d].x = fmaf(p, vv.x, acc4[d].x);
            acc4[d].y = fmaf(p, vv.y, acc4[d].y);
            acc4[d].z = fmaf(p, vv.z, acc4[d].z);
            acc4[d].w = fmaf(p, vv.w, acc4[d].w);
        }
    }

    float va[32];
    #pragma unroll
    for (int d = 0; d < 8; d++) {
        va[d * 4 + 0] = acc4[d].x; va[d * 4 + 1] = acc4[d].y;
        va[d * 4 + 2] = acc4[d].z; va[d * 4 + 3] = acc4[d].w;
    }
    uint32_t hp[16], lp[16];
    #pragma unroll
    for (int p = 0; p < 16; p++) {
        float a = va[2 * p], bb = va[2 * p + 1];
        __nv_bfloat162 hh = __floats2bfloat162_rn(a, bb);
        float ra = a - __bfloat162float(hh.x);
        float rb = bb - __bfloat162float(hh.y);
        __nv_bfloat162 ll = __floats2bfloat162_rn(ra, rb);
        hp[p] = *reinterpret_cast<uint32_t*>(&hh);
        lp[p] = *reinterpret_cast<uint32_t*>(&ll);
    }
    uint4* oh = (uint4*)(o_hi + (size_t)m * 256 + head * 32);
    uint4* ol = (uint4*)(o_lo + (size_t)m * 256 + head * 32);
    oh[0] = make_uint4(hp[0], hp[1], hp[2], hp[3]);
    oh[1] = make_uint4(hp[4], hp[5], hp[6], hp[7]);
    oh[2] = make_uint4(hp[8], hp[9], hp[10], hp[11]);
    oh[3] = make_uint4(hp[12], hp[13], hp[14], hp[15]);
    ol[0] = make_uint4(lp[0], lp[1], lp[2], lp[3]);
    ol[1] = make_uint4(lp[4], lp[5], lp[6], lp[7]);
    ol[2] = make_uint4(lp[8], lp[9], lp[10], lp[11]);
    ol[3] = make_uint4(lp[12], lp[13], lp[14], lp[15]);
}

// ---------------------------------------------------------------------------
// LayerNorm over channels + NHWC->NCHW transpose
// ---------------------------------------------------------------------------
__global__ __launch_bounds__(256) void ln_kernel(
    const float* __restrict__ proj, const float* __restrict__ gamma,
    const float* __restrict__ beta, float* __restrict__ out)
{
    __shared__ float sm[32][257];
    __shared__ float smu[32], srs[32];

    const int tid = threadIdx.x;
    const int lane = tid & 31;
    const int wp = tid >> 5;
    const int m0 = blockIdx.x * 32;
    const int b = m0 >> 16;
    const int hw = m0 & 65535;

    #pragma unroll
    for (int i = 0; i < 8; i++) {
        int idx = tid + 256 * i;
        int r = idx >> 6;
        int c4 = idx & 63;
        float4 v = *(const float4*)(proj + (size_t)(m0 + r) * 256 + c4 * 4);
        sm[r][c4 * 4 + 0] = v.x; sm[r][c4 * 4 + 1] = v.y;
        sm[r][c4 * 4 + 2] = v.z; sm[r][c4 * 4 + 3] = v.w;
    }
    __syncthreads();

    #pragma unroll
    for (int rr = 0; rr < 4; rr++) {
        int r = wp * 4 + rr;
        float sum = 0.f, sq = 0.f;
        #pragma unroll
        for (int u = 0; u < 8; u++) {
            float v = sm[r][lane + 32 * u];
            sum += v;
            sq = fmaf(v, v, sq);
        }
        #pragma unroll
        for (int off = 16; off > 0; off >>= 1) {
            sum += __shfl_xor_sync(0xFFFFFFFFu, sum, off);
            sq  += __shfl_xor_sync(0xFFFFFFFFu, sq, off);
        }
        if (lane == 0) {
            float mu = sum * (1.f / 256.f);
            smu[r] = mu;
            srs[r] = rsqrtf(sq * (1.f / 256.f) - mu * mu + 1e-5f);
        }
    }
    __syncthreads();

    #pragma unroll
    for (int it = 0; it < 32; it++) {
        int c = wp * 32 + it;
        float g = gamma[c], be = beta[c];
        float v = (sm[lane][c] - smu[lane]) * srs[lane] * g + be;
        out[(size_t)(b * 256 + c) * 65536 + hw + lane] = v;
    }
}

// ---------------------------------------------------------------------------
// Launch
// ---------------------------------------------------------------------------
extern "C" void kernel_launch(void* const* d_in, const int* in_sizes, int n_in,
                              void* d_out, int out_size)
{
    const float* x     = (const float*)d_in[0];
    const float* w_in  = (const float*)d_in[1];
    const float* b_in  = (const float*)d_in[2];
    const float* w_out = (const float*)d_in[3];
    const float* b_out = (const float*)d_in[4];
    const float* gamma = (const float*)d_in[5];
    const float* beta  = (const float*)d_in[6];
    float* out = (float*)d_out;

    float *qkv, *proj;
    __nv_bfloat16 *xh, *xl, *oh, *ol, *wih, *wil, *woh, *wol;
    cudaGetSymbolAddress((void**)&qkv, g_qkv);
    cudaGetSymbolAddress((void**)&proj, g_proj);
    cudaGetSymbolAddress((void**)&xh, g_xh);
    cudaGetSymbolAddress((void**)&xl, g_xl);
    cudaGetSymbolAddress((void**)&oh, g_oh);
    cudaGetSymbolAddress((void**)&ol, g_ol);
    cudaGetSymbolAddress((void**)&wih, g_wih);
    cudaGetSymbolAddress((void**)&wil, g_wil);
    cudaGetSymbolAddress((void**)&woh, g_woh);
    cudaGetSymbolAddress((void**)&wol, g_wol);

    cudaFuncSetAttribute(mma_gemm_kernel,
                         cudaFuncAttributeMaxDynamicSharedMemorySize, GEMM_SMEM);

    // 0) hi/lo splits (weights + transposed x)
    split_small_kernel<<<(768 * 256 + 255) / 256, 256>>>(w_in, wih, wil, 768 * 256);
    split_small_kernel<<<(256 * 256 + 255) / 256, 256>>>(w_out, woh, wol, 256 * 256);
    split_x_kernel<<<dim3(M_TOK / 128, 8), 256>>>(x, xh, xl);

    // 1) QKV projection on tensor cores (n-tiles fast for L2 A-reuse)
    mma_gemm_kernel<<<dim3(6, M_TOK / 128), 256, GEMM_SMEM>>>(
        xh, xl, wih, wil, b_in, qkv, 768);

    // 2) Windowed attention (fp32), emits bf16 hi/lo
    attn_kernel<<<NWIN * HEADS, 64>>>(qkv, oh, ol);

    // 3) Output projection on tensor cores
    mma_gemm_kernel<<<dim3(2, M_TOK / 128), 256, GEMM_SMEM>>>(
        oh, ol, woh, wol, b_out, proj, 256);

    // 4) LayerNorm + transpose to NCHW
    ln_kernel<<<M_TOK / 32, 256>>>(proj, gamma, beta, out);
}

// round 17
// speedup vs baseline: 1.0196x; 1.0196x over previous
#include <cuda_runtime.h>
#include <cuda_bf16.h>
#include <cstdint>
#include <cstddef>

// Problem constants
// x: [B=4, C=256, H=256, W=256], tokens M = B*H*W = 262144
#define M_TOK 262144
#define CDIM 256
#define HEADS 8
#define HD 32
#define WIN 8
#define TWIN 64
#define NWIN 4096

// ---------------------------------------------------------------------------
// Scratch (static __device__ arrays — allocation-free per harness rules)
// ---------------------------------------------------------------------------
__device__ float g_qkv[(size_t)M_TOK * 768];          // 805 MB
__device__ __nv_bfloat16 g_xh[(size_t)M_TOK * CDIM];  // x transposed, hi
__device__ __nv_bfloat16 g_xl[(size_t)M_TOK * CDIM];  // x transposed, lo
__device__ __nv_bfloat16 g_oh[(size_t)M_TOK * CDIM];  // attn out, hi
__device__ __nv_bfloat16 g_ol[(size_t)M_TOK * CDIM];  // attn out, lo
__device__ __nv_bfloat16 g_wih[768 * 256], g_wil[768 * 256];
__device__ __nv_bfloat16 g_woh[256 * 256], g_wol[256 * 256];

// ---------------------------------------------------------------------------
// PTX helpers (compute_103-safe: cp.async + ldmatrix + mma.sync only)
// ---------------------------------------------------------------------------
__device__ __forceinline__ uint32_t smem_u32(const void* p) {
    uint32_t a;
    asm("{ .reg .u64 t; cvta.to.shared.u64 t, %1; cvt.u32.u64 %0, t; }"
        : "=r"(a) : "l"(p));
    return a;
}

__device__ __forceinline__ void cp16(uint32_t dst, const void* src) {
    asm volatile("cp.async.cg.shared.global [%0], [%1], 16;"
                 :: "r"(dst), "l"(src));
}

#define LDSM4(r, a) \
    asm volatile("ldmatrix.sync.aligned.m8n8.x4.shared.b16 {%0,%1,%2,%3}, [%4];" \
        : "=r"((r)[0]), "=r"((r)[1]), "=r"((r)[2]), "=r"((r)[3]) : "r"(a))

#define MMA16816(c, a, b0, b1) \
    asm volatile("mma.sync.aligned.m16n8k16.row.col.f32.bf16.bf16.f32 " \
        "{%0,%1,%2,%3}, {%4,%5,%6,%7}, {%8,%9}, {%0,%1,%2,%3};" \
        : "+f"((c)[0]), "+f"((c)[1]), "+f"((c)[2]), "+f"((c)[3]) \
        : "r"((a)[0]), "r"((a)[1]), "r"((a)[2]), "r"((a)[3]), "r"(b0), "r"(b1))

// ---------------------------------------------------------------------------
// Split kernels: fp32 -> (bf16 hi, bf16 lo)
// ---------------------------------------------------------------------------
__global__ __launch_bounds__(256) void split_small_kernel(
    const float* __restrict__ in, __nv_bfloat16* __restrict__ hi,
    __nv_bfloat16* __restrict__ lo, int n)
{
    int i = blockIdx.x * 256 + threadIdx.x;
    if (i < n) {
        float v = in[i];
        __nv_bfloat16 h = __float2bfloat16(v);
        hi[i] = h;
        lo[i] = __float2bfloat16(v - __bfloat162float(h));
    }
}

// x [4][256][65536] NCHW -> xT [m][256] bf16 hi/lo (transpose + split)
__global__ __launch_bounds__(256) void split_x_kernel(
    const float* __restrict__ x, __nv_bfloat16* __restrict__ hi,
    __nv_bfloat16* __restrict__ lo)
{
    __shared__ float s[32][132];
    const int tid = threadIdx.x;
    const int m0 = blockIdx.x * 128;
    const int c0 = blockIdx.y * 32;
    const int b = m0 >> 16;
    const int hw0 = m0 & 65535;
    const float* xb = x + ((size_t)b * 256 + c0) * 65536 + hw0;

    #pragma unroll
    for (int i = 0; i < 4; i++) {
        int idx = tid + 256 * i;       // 1024 float4 slots = 32c x 32(m4)
        int c = idx >> 5, m4 = idx & 31;
        float4 v = *(const float4*)(xb + (size_t)c * 65536 + m4 * 4);
        *(float4*)&s[c][m4 * 4] = v;
    }
    __syncthreads();

    const int m = tid >> 1;
    const int half = tid & 1;
    uint32_t hp[8], lp[8];
    #pragma unroll
    for (int p = 0; p < 8; p++) {
        float a = s[half * 16 + 2 * p][m];
        float bb = s[half * 16 + 2 * p + 1][m];
        __nv_bfloat162 hh = __floats2bfloat162_rn(a, bb);
        float ra = a - __bfloat162float(hh.x);
        float rb = bb - __bfloat162float(hh.y);
        __nv_bfloat162 ll = __floats2bfloat162_rn(ra, rb);
        hp[p] = *reinterpret_cast<uint32_t*>(&hh);
        lp[p] = *reinterpret_cast<uint32_t*>(&ll);
    }
    size_t o = (size_t)(m0 + m) * 256 + c0 + half * 16;
    ((uint4*)(hi + o))[0] = make_uint4(hp[0], hp[1], hp[2], hp[3]);
    ((uint4*)(hi + o))[1] = make_uint4(hp[4], hp[5], hp[6], hp[7]);
    ((uint4*)(lo + o))[0] = make_uint4(lp[0], lp[1], lp[2], lp[3]);
    ((uint4*)(lo + o))[1] = make_uint4(lp[4], lp[5], lp[6], lp[7]);
}

// ---------------------------------------------------------------------------
// bf16 mma.sync GEMM (QKV): out[m, n] = sum_k A[m,k]*B[n,k] + bias[n]
//  CTA tile 128x128, BK=32, 2-stage cp.async, 3-term compensated product.
// ---------------------------------------------------------------------------
#define TILE_B 10240           // 128 * 80 bytes
#define STAGE_B (4 * TILE_B)   // Ah, Al, Bh, Bl
#define GEMM_SMEM (2 * STAGE_B)

__device__ __forceinline__ void load_tile32(uint32_t dst, const __nv_bfloat16* src,
                                            int r0, int k0, int tid) {
    #pragma unroll
    for (int i = 0; i < 2; i++) {
        int idx = tid + 256 * i;          // 512 x 16B chunks
        int row = idx >> 2, cc = idx & 3;
        cp16(dst + row * 80 + cc * 16,
             src + (size_t)(r0 + row) * 256 + k0 + cc * 8);
    }
}

__global__ __launch_bounds__(256) void mma_gemm_kernel(
    const __nv_bfloat16* __restrict__ Ah, const __nv_bfloat16* __restrict__ Al,
    const __nv_bfloat16* __restrict__ Bh, const __nv_bfloat16* __restrict__ Bl,
    const float* __restrict__ bias, float* __restrict__ out, int ldout)
{
    extern __shared__ char smem[];
    const int tid = threadIdx.x;
    const int wid = tid >> 5, lane = tid & 31;
    const int wm = wid & 3, wn = wid >> 2;       // 4 x 2 warp grid
    const int n0 = blockIdx.x * 128, m0 = blockIdx.y * 128;
    const uint32_t sb = smem_u32(smem);

    const uint32_t aRowB = (uint32_t)(wm * 32 + (lane & 15)) * 80 + (lane >> 4) * 16;
    const uint32_t bRowB = (uint32_t)(wn * 64 + (lane >> 4) * 8 + (lane & 7)) * 80
                         + ((lane >> 3) & 1) * 16;

    #define LOAD_STAGE(s) do {                                   \
        int _k = (s) * 32;                                       \
        uint32_t _b = sb + ((s) & 1) * STAGE_B;                  \
        load_tile32(_b,              Ah, m0, _k, tid);           \
        load_tile32(_b + TILE_B,     Al, m0, _k, tid);           \
        load_tile32(_b + 2 * TILE_B, Bh, n0, _k, tid);           \
        load_tile32(_b + 3 * TILE_B, Bl, n0, _k, tid);           \
        asm volatile("cp.async.commit_group;" ::: "memory");     \
    } while (0)

    LOAD_STAGE(0);
    LOAD_STAGE(1);

    float c[2][8][4];
    #pragma unroll
    for (int mi = 0; mi < 2; mi++)
        #pragma unroll
        for (int nj = 0; nj < 8; nj++)
            #pragma unroll
            for (int q = 0; q < 4; q++) c[mi][nj][q] = 0.f;

    #pragma unroll 1
    for (int s = 0; s < 8; s++) {
        if (s < 7) asm volatile("cp.async.wait_group 1;" ::: "memory");
        else       asm volatile("cp.async.wait_group 0;" ::: "memory");
        __syncthreads();

        const uint32_t base = sb + (s & 1) * STAGE_B;
        #pragma unroll
        for (int kk = 0; kk < 2; kk++) {
            const uint32_t ko = kk * 32;
            uint32_t ah[2][4], al[2][4], bh[4][4], bl[4][4];
            #pragma unroll
            for (int mi = 0; mi < 2; mi++) {
                uint32_t ra = base + aRowB + mi * 16 * 80 + ko;
                LDSM4(ah[mi], ra);
                LDSM4(al[mi], ra + TILE_B);
            }
            #pragma unroll
            for (int g = 0; g < 4; g++) {
                uint32_t rb = base + 2 * TILE_B + bRowB + g * 16 * 80 + ko;
                LDSM4(bh[g], rb);
                LDSM4(bl[g], rb + TILE_B);
            }
            #pragma unroll
            for (int mi = 0; mi < 2; mi++)
                #pragma unroll
                for (int g = 0; g < 4; g++)
                    #pragma unroll
                    for (int h = 0; h < 2; h++) {
                        float* cc = c[mi][2 * g + h];
                        MMA16816(cc, ah[mi], bh[g][2 * h], bh[g][2 * h + 1]);
                        MMA16816(cc, ah[mi], bl[g][2 * h], bl[g][2 * h + 1]);
                        MMA16816(cc, al[mi], bh[g][2 * h], bh[g][2 * h + 1]);
                    }
        }
        __syncthreads();
        if (s + 2 < 8) LOAD_STAGE(s + 2);
    }
    #undef LOAD_STAGE

    #pragma unroll
    for (int mi = 0; mi < 2; mi++) {
        const int row = m0 + wm * 32 + mi * 16 + (lane >> 2);
        #pragma unroll
        for (int nj = 0; nj < 8; nj++) {
            const int col = n0 + wn * 64 + nj * 8 + (lane & 3) * 2;
            const float2 bv = *(const float2*)(bias + col);
            float2 v0 = make_float2(c[mi][nj][0] + bv.x, c[mi][nj][1] + bv.y);
            float2 v1 = make_float2(c[mi][nj][2] + bv.x, c[mi][nj][3] + bv.y);
            *(float2*)(out + (size_t)row * ldout + col) = v0;
            *(float2*)(out + (size_t)(row + 8) * ldout + col) = v1;
        }
    }
}

// ---------------------------------------------------------------------------
// Fused out-projection GEMM + bias + channel-LayerNorm + NCHW store.
//  CTA tile: 64 m-rows x 256 n-cols (full C), 8 warps as 2m x 4n, warp 32x64.
// ---------------------------------------------------------------------------
#define OA_TILE_B 5120          // 64 * 80
#define OB_TILE_B 20480         // 256 * 80
#define OSTAGE_B (2 * OA_TILE_B + 2 * OB_TILE_B)   // 51200
#define OUTLN_SMEM (2 * OSTAGE_B)                  // 102400 (>= 64*257*4 epilogue)

__global__ __launch_bounds__(256) void outln_kernel(
    const __nv_bfloat16* __restrict__ Ah, const __nv_bfloat16* __restrict__ Al,
    const __nv_bfloat16* __restrict__ Bh, const __nv_bfloat16* __restrict__ Bl,
    const float* __restrict__ bias, const float* __restrict__ gamma,
    const float* __restrict__ beta, float* __restrict__ out)
{
    extern __shared__ char smem[];
    __shared__ float smu[64], srs[64];
    const int tid = threadIdx.x;
    const int wid = tid >> 5, lane = tid & 31;
    const int wm = wid & 1, wn = wid >> 1;       // 2m x 4n warp grid
    const int m0 = blockIdx.x * 64;
    const uint32_t sb = smem_u32(smem);

    const uint32_t aRowB = (uint32_t)(wm * 32 + (lane & 15)) * 80 + (lane >> 4) * 16;
    const uint32_t bRowB = (uint32_t)(wn * 64 + (lane >> 4) * 8 + (lane & 7)) * 80
                         + ((lane >> 3) & 1) * 16;

    #define OLOAD_STAGE(s) do {                                            \
        int _k = (s) * 32;                                                 \
        uint32_t _b = sb + ((s) & 1) * OSTAGE_B;                           \
        {                                                                  \
            int row = tid >> 2, cc = tid & 3;                              \
            cp16(_b + row * 80 + cc * 16,                                  \
                 Ah + (size_t)(m0 + row) * 256 + _k + cc * 8);             \
            cp16(_b + OA_TILE_B + row * 80 + cc * 16,                      \
                 Al + (size_t)(m0 + row) * 256 + _k + cc * 8);             \
        }                                                                  \
        _Pragma("unroll")                                                  \
        for (int i = 0; i < 4; i++) {                                      \
            int idx = tid + 256 * i;                                       \
            int row = idx >> 2, cc = idx & 3;                              \
            cp16(_b + 2 * OA_TILE_B + row * 80 + cc * 16,                  \
                 Bh + (size_t)row * 256 + _k + cc * 8);                    \
            cp16(_b + 2 * OA_TILE_B + OB_TILE_B + row * 80 + cc * 16,      \
                 Bl + (size_t)row * 256 + _k + cc * 8);                    \
        }                                                                  \
        asm volatile("cp.async.commit_group;" ::: "memory");               \
    } while (0)

    OLOAD_STAGE(0);
    OLOAD_STAGE(1);

    float c[2][8][4];
    #pragma unroll
    for (int mi = 0; mi < 2; mi++)
        #pragma unroll
        for (int nj = 0; nj < 8; nj++)
            #pragma unroll
            for (int q = 0; q < 4; q++) c[mi][nj][q] = 0.f;

    #pragma unroll 1
    for (int s = 0; s < 8; s++) {
        if (s < 7) asm volatile("cp.async.wait_group 1;" ::: "memory");
        else       asm volatile("cp.async.wait_group 0;" ::: "memory");
        __syncthreads();

        const uint32_t base = sb + (s & 1) * OSTAGE_B;
        #pragma unroll
        for (int kk = 0; kk < 2; kk++) {
            const uint32_t ko = kk * 32;
            uint32_t ah[2][4], al[2][4], bh[4][4], bl[4][4];
            #pragma unroll
            for (int mi = 0; mi < 2; mi++) {
                uint32_t ra = base + aRowB + mi * 16 * 80 + ko;
                LDSM4(ah[mi], ra);
                LDSM4(al[mi], ra + OA_TILE_B);
            }
            #pragma unroll
            for (int g = 0; g < 4; g++) {
                uint32_t rb = base + 2 * OA_TILE_B + bRowB + g * 16 * 80 + ko;
                LDSM4(bh[g], rb);
                LDSM4(bl[g], rb + OB_TILE_B);
            }
            #pragma unroll
            for (int mi = 0; mi < 2; mi++)
                #pragma unroll
                for (int g = 0; g < 4; g++)
                    #pragma unroll
                    for (int h = 0; h < 2; h++) {
                        float* cc = c[mi][2 * g + h];
                        MMA16816(cc, ah[mi], bh[g][2 * h], bh[g][2 * h + 1]);
                        MMA16816(cc, ah[mi], bl[g][2 * h], bl[g][2 * h + 1]);
                        MMA16816(cc, al[mi], bh[g][2 * h], bh[g][2 * h + 1]);
                    }
        }
        __syncthreads();
        if (s + 2 < 8) OLOAD_STAGE(s + 2);
    }
    #undef OLOAD_STAGE

    // ---- Epilogue: fragments + bias -> smem tile (64 x 257) ----
    float* dt = (float*)smem;
    #pragma unroll
    for (int mi = 0; mi < 2; mi++) {
        const int r = wm * 32 + mi * 16 + (lane >> 2);
        #pragma unroll
        for (int nj = 0; nj < 8; nj++) {
            const int col = wn * 64 + nj * 8 + (lane & 3) * 2;
            const float2 bv = *(const float2*)(bias + col);
            dt[r * 257 + col]           = c[mi][nj][0] + bv.x;
            dt[r * 257 + col + 1]       = c[mi][nj][1] + bv.y;
            dt[(r + 8) * 257 + col]     = c[mi][nj][2] + bv.x;
            dt[(r + 8) * 257 + col + 1] = c[mi][nj][3] + bv.y;
        }
    }
    __syncthreads();

    // ---- per-token mean / rstd over 256 channels (8 rows per warp) ----
    #pragma unroll
    for (int rr = 0; rr < 8; rr++) {
        int r = wid * 8 + rr;
        float sum = 0.f, sq = 0.f;
        #pragma unroll
        for (int u = 0; u < 8; u++) {
            float v = dt[r * 257 + lane + 32 * u];
            sum += v;
            sq = fmaf(v, v, sq);
        }
        #pragma unroll
        for (int off = 16; off > 0; off >>= 1) {
            sum += __shfl_xor_sync(0xFFFFFFFFu, sum, off);
            sq  += __shfl_xor_sync(0xFFFFFFFFu, sq, off);
        }
        if (lane == 0) {
            float mu = sum * (1.f / 256.f);
            smu[r] = mu;
            srs[r] = rsqrtf(sq * (1.f / 256.f) - mu * mu + 1e-5f);
        }
    }
    __syncthreads();

    // ---- normalize + write NCHW (contiguous 32-float runs per channel) ----
    const int b = m0 >> 16;
    const int hw = m0 & 65535;
    const float mu0 = smu[lane], rs0 = srs[lane];
    const float mu1 = smu[lane + 32], rs1 = srs[lane + 32];
    #pragma unroll
    for (int it = 0; it < 32; it++) {
        int ch = wid * 32 + it;                      // uniform within warp
        float g = gamma[ch], be = beta[ch];
        float v0 = (dt[lane * 257 + ch] - mu0) * rs0 * g + be;
        float v1 = (dt[(lane + 32) * 257 + ch] - mu1) * rs1 * g + be;
        size_t o = (size_t)(b * 256 + ch) * 65536 + hw;
        out[o + lane] = v0;
        out[o + lane + 32] = v1;
    }
}

// ---------------------------------------------------------------------------
// Windowed attention (fp32). One 64-thread block per (window, head).
// Outputs bf16 hi/lo directly for the out-proj GEMM.
// ---------------------------------------------------------------------------
__global__ __launch_bounds__(64) void attn_kernel(
    const float* __restrict__ qkv,
    __nv_bfloat16* __restrict__ o_hi, __nv_bfloat16* __restrict__ o_lo)
{
    const int bid = blockIdx.x;
    const int head = bid & 7;
    const int win = bid >> 3;
    const int b = win >> 10;
    const int rem = win & 1023;
    const int hn = rem >> 5, wn = rem & 31;

    const int t = threadIdx.x;
    const int s1 = t >> 3, s2 = t & 7;
    const int m = (b << 16) + ((hn * 8 + s1) << 8) + (wn * 8 + s2);

    __shared__ float4 ks[TWIN][8];
    __shared__ float4 vs[TWIN][8];

    const float* qp = qkv + (size_t)m * 768 + head * 32;
    float4 q[8];
    #pragma unroll
    for (int d = 0; d < 8; d++) {
        q[d]     = ((const float4*)(qp))[d];
        ks[t][d] = ((const float4*)(qp + 256))[d];
        vs[t][d] = ((const float4*)(qp + 512))[d];
    }
    __syncthreads();

    float s[TWIN];
    #pragma unroll
    for (int j = 0; j < TWIN; j++) {
        float acc = 0.f;
        #pragma unroll
        for (int d = 0; d < 8; d++) {
            float4 kv = ks[j][d];
            acc = fmaf(q[d].x, kv.x, acc);
            acc = fmaf(q[d].y, kv.y, acc);
            acc = fmaf(q[d].z, kv.z, acc);
            acc = fmaf(q[d].w, kv.w, acc);
        }
        s[j] = acc * 0.17677669529663687f;
    }

    float mx = s[0];
    #pragma unroll
    for (int j = 1; j < TWIN; j++) mx = fmaxf(mx, s[j]);
    float sum = 0.f;
    #pragma unroll
    for (int j = 0; j < TWIN; j++) { s[j] = __expf(s[j] - mx); sum += s[j]; }
    const float inv = 1.f / sum;

    float4 acc4[8];
    #pragma unroll
    for (int d = 0; d < 8; d++) acc4[d] = make_float4(0.f, 0.f, 0.f, 0.f);
    #pragma unroll
    for (int j = 0; j < TWIN; j++) {
        const float p = s[j] * inv;
        #pragma unroll
        for (int d = 0; d < 8; d++) {
            float4 vv = vs[j][d];
            acc4[d].x = fmaf(p, vv.x, acc4[d].x);
            acc4[d].y = fmaf(p, vv.y, acc4[d].y);
            acc4[d].z = fmaf(p, vv.z, acc4[d].z);
            acc4[d].w = fmaf(p, vv.w, acc4[d].w);
        }
    }

    float va[32];
    #pragma unroll
    for (int d = 0; d < 8; d++) {
        va[d * 4 + 0] = acc4[d].x; va[d * 4 + 1] = acc4[d].y;
        va[d * 4 + 2] = acc4[d].z; va[d * 4 + 3] = acc4[d].w;
    }
    uint32_t hp[16], lp[16];
    #pragma unroll
    for (int p = 0; p < 16; p++) {
        float a = va[2 * p], bb = va[2 * p + 1];
        __nv_bfloat162 hh = __floats2bfloat162_rn(a, bb);
        float ra = a - __bfloat162float(hh.x);
        float rb = bb - __bfloat162float(hh.y);
        __nv_bfloat162 ll = __floats2bfloat162_rn(ra, rb);
        hp[p] = *reinterpret_cast<uint32_t*>(&hh);
        lp[p] = *reinterpret_cast<uint32_t*>(&ll);
    }
    uint4* oh = (uint4*)(o_hi + (size_t)m * 256 + head * 32);
    uint4* ol = (uint4*)(o_lo + (size_t)m * 256 + head * 32);
    oh[0] = make_uint4(hp[0], hp[1], hp[2], hp[3]);
    oh[1] = make_uint4(hp[4], hp[5], hp[6], hp[7]);
    oh[2] = make_uint4(hp[8], hp[9], hp[10], hp[11]);
    oh[3] = make_uint4(hp[12], hp[13], hp[14], hp[15]);
    ol[0] = make_uint4(lp[0], lp[1], lp[2], lp[3]);
    ol[1] = make_uint4(lp[4], lp[5], lp[6], lp[7]);
    ol[2] = make_uint4(lp[8], lp[9], lp[10], lp[11]);
    ol[3] = make_uint4(lp[12], lp[13], lp[14], lp[15]);
}

// ---------------------------------------------------------------------------
// Launch
// ---------------------------------------------------------------------------
extern "C" void kernel_launch(void* const* d_in, const int* in_sizes, int n_in,
                              void* d_out, int out_size)
{
    const float* x     = (const float*)d_in[0];
    const float* w_in  = (const float*)d_in[1];
    const float* b_in  = (const float*)d_in[2];
    const float* w_out = (const float*)d_in[3];
    const float* b_out = (const float*)d_in[4];
    const float* gamma = (const float*)d_in[5];
    const float* beta  = (const float*)d_in[6];
    float* out = (float*)d_out;

    float *qkv;
    __nv_bfloat16 *xh, *xl, *oh, *ol, *wih, *wil, *woh, *wol;
    cudaGetSymbolAddress((void**)&qkv, g_qkv);
    cudaGetSymbolAddress((void**)&xh, g_xh);
    cudaGetSymbolAddress((void**)&xl, g_xl);
    cudaGetSymbolAddress((void**)&oh, g_oh);
    cudaGetSymbolAddress((void**)&ol, g_ol);
    cudaGetSymbolAddress((void**)&wih, g_wih);
    cudaGetSymbolAddress((void**)&wil, g_wil);
    cudaGetSymbolAddress((void**)&woh, g_woh);
    cudaGetSymbolAddress((void**)&wol, g_wol);

    cudaFuncSetAttribute(mma_gemm_kernel,
                         cudaFuncAttributeMaxDynamicSharedMemorySize, GEMM_SMEM);
    cudaFuncSetAttribute(outln_kernel,
                         cudaFuncAttributeMaxDynamicSharedMemorySize, OUTLN_SMEM);

    // 0) hi/lo splits (weights + transposed x)
    split_small_kernel<<<(768 * 256 + 255) / 256, 256>>>(w_in, wih, wil, 768 * 256);
    split_small_kernel<<<(256 * 256 + 255) / 256, 256>>>(w_out, woh, wol, 256 * 256);
    split_x_kernel<<<dim3(M_TOK / 128, 8), 256>>>(x, xh, xl);

    // 1) QKV projection on tensor cores (n-tiles fast for L2 A-reuse)
    mma_gemm_kernel<<<dim3(6, M_TOK / 128), 256, GEMM_SMEM>>>(
        xh, xl, wih, wil, b_in, qkv, 768);

    // 2) Windowed attention (fp32), emits bf16 hi/lo
    attn_kernel<<<NWIN * HEADS, 64>>>(qkv, oh, ol);

    // 3) Fused out-projection + bias + LayerNorm + NCHW store
    outln_kernel<<<M_TOK / 64, 256, OUTLN_SMEM>>>(
        oh, ol, woh, wol, b_out, gamma, beta, out);
}